// round 2
// baseline (speedup 1.0000x reference)
#include <cuda_runtime.h>
#include <cuda_bf16.h>
#include <cstdint>
#include <cstddef>

// Problem dims (fixed by dataset)
#define B_IMG   128
#define C_DIM   64
#define P_DIM   441           // 21*21
#define NWAY    50
#define M_DIM   2205
#define NROWS   (B_IMG * P_DIM)     // 56448
#define NCHUNK  35                  // ceil(2205/64)
#define SM_STRIDE 72                // bf16 elems per support-descriptor row in smem (144B, conflict-free)

// Scratch: normalized bf16 descriptors (static device globals — no allocation)
__device__ __nv_bfloat16 g_qn[(size_t)NROWS * C_DIM];            // [row][c], row = b*441+p
__device__ __nv_bfloat16 g_sn[(size_t)NWAY * M_DIM * C_DIM];     // [j][m][c]

// ---------------------------------------------------------------------------
// Precompute: L2-normalize descriptors, convert to bf16.
// One warp per descriptor; lane covers c and c+32 (strided loads, L2-friendly).
// ---------------------------------------------------------------------------
__global__ void prep_q(const float* __restrict__ q) {
    int idx = blockIdx.x * 8 + (threadIdx.x >> 5);
    if (idx >= NROWS) return;
    int lane = threadIdx.x & 31;
    int b = idx / P_DIM, p = idx % P_DIM;
    const float* base = q + (size_t)b * C_DIM * P_DIM + p;
    float v0 = base[(size_t)lane * P_DIM];
    float v1 = base[(size_t)(lane + 32) * P_DIM];
    float ss = v0 * v0 + v1 * v1;
#pragma unroll
    for (int off = 16; off; off >>= 1) ss += __shfl_xor_sync(0xffffffffu, ss, off);
    float r = rsqrtf(ss);
    g_qn[(size_t)idx * C_DIM + lane]      = __float2bfloat16(v0 * r);
    g_qn[(size_t)idx * C_DIM + lane + 32] = __float2bfloat16(v1 * r);
}

__global__ void prep_s(const float* __restrict__ S) {
    int idx = blockIdx.x * 8 + (threadIdx.x >> 5);
    if (idx >= NWAY * M_DIM) return;
    int lane = threadIdx.x & 31;
    int j = idx / M_DIM, m = idx % M_DIM;
    const float* base = S + (size_t)j * C_DIM * M_DIM + m;
    float v0 = base[(size_t)lane * M_DIM];
    float v1 = base[(size_t)(lane + 32) * M_DIM];
    float ss = v0 * v0 + v1 * v1;
#pragma unroll
    for (int off = 16; off; off >>= 1) ss += __shfl_xor_sync(0xffffffffu, ss, off);
    float r = rsqrtf(ss);
    g_sn[(size_t)idx * C_DIM + lane]      = __float2bfloat16(v0 * r);
    g_sn[(size_t)idx * C_DIM + lane + 32] = __float2bfloat16(v1 * r);
}

// ---------------------------------------------------------------------------
// mma.sync m16n8k16 bf16, fp32 accum
// ---------------------------------------------------------------------------
__device__ __forceinline__ void mma16816(float& d0, float& d1, float& d2, float& d3,
                                         uint32_t a0, uint32_t a1, uint32_t a2, uint32_t a3,
                                         uint32_t b0, uint32_t b1) {
    asm volatile(
        "mma.sync.aligned.m16n8k16.row.col.f32.bf16.bf16.f32 "
        "{%0,%1,%2,%3}, {%4,%5,%6,%7}, {%8,%9}, {%0,%1,%2,%3};"
        : "+f"(d0), "+f"(d1), "+f"(d2), "+f"(d3)
        : "r"(a0), "r"(a1), "r"(a2), "r"(a3), "r"(b0), "r"(b1));
}

// Streaming top-3 insert: rare-taken branch, ~2 inst common path
__device__ __forceinline__ void upd(float v, float& t0, float& t1, float& t2) {
    if (v > t2) {
        if (v > t1) {
            t2 = t1;
            if (v > t0) { t1 = t0; t0 = v; }
            else        { t1 = v; }
        } else {
            t2 = v;
        }
    }
}

// Branchless insert for cross-lane merges (runs a handful of times)
__device__ __forceinline__ void ins3(float v, float& t0, float& t1, float& t2) {
    float a0 = fmaxf(t0, v), b0 = fminf(t0, v);
    float a1 = fmaxf(t1, b0), b1 = fminf(t1, b0);
    t0 = a0; t1 = a1; t2 = fmaxf(t2, b1);
}

// cp.async one 64-column support chunk into smem, zero-fill past M
__device__ __forceinline__ void load_chunk(int chunk, __nv_bfloat16* buf,
                                           const __nv_bfloat16* snj, int tid) {
    int m0 = chunk * 64;
#pragma unroll 1
    for (int i = tid; i < 512; i += 224) {
        int col = i >> 3, seg = i & 7;
        int m = m0 + col;
        int valid = (m < M_DIM);
        const __nv_bfloat16* src = snj + (size_t)(valid ? m : 0) * C_DIM + seg * 8;
        uint32_t daddr = (uint32_t)__cvta_generic_to_shared(buf + col * SM_STRIDE + seg * 8);
        int sz = valid ? 16 : 0;
        asm volatile("cp.async.cg.shared.global [%0], [%1], 16, %2;"
                     :: "r"(daddr), "l"(src), "r"(sz));
    }
}

template <bool GUARD>
__device__ __forceinline__ void process_chunk(const __nv_bfloat16* sm,
                                              const uint32_t (&afr)[4][4][4],
                                              float (&t0)[4][2], float (&t1)[4][2], float (&t2)[4][2],
                                              int lane, int m0) {
    int colq = lane >> 2;
    int kq = (lane & 3) * 2;
#pragma unroll
    for (int st = 0; st < 8; st++) {
        uint32_t bf[4][2];
        const __nv_bfloat16* base = sm + (st * 8 + colq) * SM_STRIDE + kq;
#pragma unroll
        for (int kk = 0; kk < 4; kk++) {
            bf[kk][0] = *(const uint32_t*)(base + kk * 16);
            bf[kk][1] = *(const uint32_t*)(base + kk * 16 + 8);
        }
        int mcol = m0 + st * 8 + (lane & 3) * 2;  // column of d0/d2; d1/d3 at mcol+1
#pragma unroll
        for (int g = 0; g < 4; g++) {
            float d0 = 0.f, d1 = 0.f, d2 = 0.f, d3 = 0.f;
#pragma unroll
            for (int kk = 0; kk < 4; kk++)
                mma16816(d0, d1, d2, d3,
                         afr[g][kk][0], afr[g][kk][1], afr[g][kk][2], afr[g][kk][3],
                         bf[kk][0], bf[kk][1]);
            if (!GUARD || mcol < M_DIM) {
                upd(d0, t0[g][0], t1[g][0], t2[g][0]);
                upd(d2, t0[g][1], t1[g][1], t2[g][1]);
            }
            if (!GUARD || mcol + 1 < M_DIM) {
                upd(d1, t0[g][0], t1[g][0], t2[g][0]);
                upd(d3, t0[g][1], t1[g][1], t2[g][1]);
            }
        }
    }
}

// ---------------------------------------------------------------------------
// Main fused kernel: CTA = (class j, image b). 7 warps * 4 groups * 16 rows
// = 448 rows (441 valid). A fragments register-resident for the whole M sweep.
// ---------------------------------------------------------------------------
__global__ __launch_bounds__(224, 2)
void knn_main(float* __restrict__ out) {
    __shared__ __nv_bfloat16 sbuf[2][64 * SM_STRIDE];
    __shared__ float wsum[7];

    int j = blockIdx.x;
    int b = blockIdx.y;
    int tid = threadIdx.x;
    int warp = tid >> 5;
    int lane = tid & 31;

    const __nv_bfloat16* snj = g_sn + (size_t)j * M_DIM * C_DIM;

    // Load A fragments (held in registers the whole kernel). Rows >= 441 -> zeros.
    uint32_t afr[4][4][4];
    int c0 = (lane & 3) * 2;
#pragma unroll
    for (int g = 0; g < 4; g++) {
        int r0 = (warp * 4 + g) * 16 + (lane >> 2);
        int r1 = r0 + 8;
        bool v0 = r0 < P_DIM, v1 = r1 < P_DIM;
        const uint32_t* row0 = (const uint32_t*)(g_qn + ((size_t)b * P_DIM + (v0 ? r0 : 0)) * C_DIM);
        const uint32_t* row1 = (const uint32_t*)(g_qn + ((size_t)b * P_DIM + (v1 ? r1 : 0)) * C_DIM);
#pragma unroll
        for (int kk = 0; kk < 4; kk++) {
            int cw = (c0 + kk * 16) >> 1;  // u32 index into the 64-ch row
            afr[g][kk][0] = v0 ? row0[cw]     : 0u;
            afr[g][kk][1] = v1 ? row1[cw]     : 0u;
            afr[g][kk][2] = v0 ? row0[cw + 4] : 0u;
            afr[g][kk][3] = v1 ? row1[cw + 4] : 0u;
        }
    }

    float t0[4][2], t1[4][2], t2[4][2];
#pragma unroll
    for (int g = 0; g < 4; g++)
#pragma unroll
        for (int h = 0; h < 2; h++) { t0[g][h] = -1e30f; t1[g][h] = -1e30f; t2[g][h] = -1e30f; }

    load_chunk(0, sbuf[0], snj, tid);
    asm volatile("cp.async.commit_group;");

#pragma unroll 1
    for (int chunk = 0; chunk < NCHUNK; chunk++) {
        if (chunk + 1 < NCHUNK) load_chunk(chunk + 1, sbuf[(chunk + 1) & 1], snj, tid);
        asm volatile("cp.async.commit_group;");
        asm volatile("cp.async.wait_group 1;");
        __syncthreads();
        const __nv_bfloat16* sm = sbuf[chunk & 1];
        if (chunk == NCHUNK - 1)
            process_chunk<true>(sm, afr, t0, t1, t2, lane, chunk * 64);
        else
            process_chunk<false>(sm, afr, t0, t1, t2, lane, chunk * 64);
        __syncthreads();
    }

    // Merge top-3 across the 4 lanes of each quad (they saw disjoint columns)
    float acc = 0.f;
#pragma unroll
    for (int g = 0; g < 4; g++) {
#pragma unroll
        for (int h = 0; h < 2; h++) {
            float x0 = t0[g][h], x1 = t1[g][h], x2 = t2[g][h];
#pragma unroll
            for (int off = 1; off <= 2; off <<= 1) {
                float y0 = __shfl_xor_sync(0xffffffffu, x0, off);
                float y1 = __shfl_xor_sync(0xffffffffu, x1, off);
                float y2 = __shfl_xor_sync(0xffffffffu, x2, off);
                ins3(y0, x0, x1, x2);
                ins3(y1, x0, x1, x2);
                ins3(y2, x0, x1, x2);
            }
            acc += x0 + x1 + x2;
        }
    }
    if (lane & 3) acc = 0.f;  // each quad's 4 lanes now hold identical triples
#pragma unroll
    for (int off = 16; off; off >>= 1) acc += __shfl_xor_sync(0xffffffffu, acc, off);
    if (lane == 0) wsum[warp] = acc;
    __syncthreads();
    if (tid == 0) {
        float s = 0.f;
#pragma unroll
        for (int w = 0; w < 7; w++) s += wsum[w];
        out[b * NWAY + j] = s;  // inner[b][j]
    }
}

// ---------------------------------------------------------------------------
extern "C" void kernel_launch(void* const* d_in, const int* in_sizes, int n_in,
                              void* d_out, int out_size) {
    const float* q = (const float*)d_in[0];
    const float* S = (const float*)d_in[1];
    float* out = (float*)d_out;

    prep_q<<<(NROWS + 7) / 8, 256>>>(q);
    prep_s<<<(NWAY * M_DIM + 7) / 8, 256>>>(S);
    knn_main<<<dim3(NWAY, B_IMG), 224>>>(out);
}

// round 9
// speedup vs baseline: 1.5335x; 1.5335x over previous
#include <cuda_runtime.h>
#include <cuda_bf16.h>
#include <cstdint>
#include <cstddef>

// Problem dims (fixed by dataset)
#define B_IMG   128
#define C_DIM   64
#define P_DIM   441           // 21*21
#define NWAY    50
#define M_DIM   2205
#define NROWS   (B_IMG * P_DIM)     // 56448
#define NDESC_S (NWAY * M_DIM)      // 110250
#define NCHUNK  35                  // ceil(2205/64)
#define SM_STRIDE 72                // bf16 elems per support-descriptor row in smem (144B, conflict-free)

// Scratch: normalized bf16 descriptors (static device globals — no allocation)
__device__ __nv_bfloat16 g_qn[(size_t)NROWS * C_DIM];            // [row][c], row = b*441+p
__device__ __nv_bfloat16 g_sn[(size_t)NDESC_S * C_DIM];          // [j][m][c]

// ---------------------------------------------------------------------------
// Precompute (single kernel => knn_main is every odd launch; ncu -s 5 hits it).
// One warp per descriptor: L2-normalize over C=64, convert to bf16.
// ---------------------------------------------------------------------------
__global__ void prep_all(const float* __restrict__ q, const float* __restrict__ S) {
    int idx = blockIdx.x * 8 + (threadIdx.x >> 5);
    int lane = threadIdx.x & 31;
    if (idx < NROWS) {
        int b = idx / P_DIM, p = idx % P_DIM;
        const float* base = q + (size_t)b * C_DIM * P_DIM + p;
        float v0 = base[(size_t)lane * P_DIM];
        float v1 = base[(size_t)(lane + 32) * P_DIM];
        float ss = v0 * v0 + v1 * v1;
#pragma unroll
        for (int off = 16; off; off >>= 1) ss += __shfl_xor_sync(0xffffffffu, ss, off);
        float r = rsqrtf(ss);
        g_qn[(size_t)idx * C_DIM + lane]      = __float2bfloat16(v0 * r);
        g_qn[(size_t)idx * C_DIM + lane + 32] = __float2bfloat16(v1 * r);
    } else if (idx < NROWS + NDESC_S) {
        int sidx = idx - NROWS;
        int j = sidx / M_DIM, m = sidx % M_DIM;
        const float* base = S + (size_t)j * C_DIM * M_DIM + m;
        float v0 = base[(size_t)lane * M_DIM];
        float v1 = base[(size_t)(lane + 32) * M_DIM];
        float ss = v0 * v0 + v1 * v1;
#pragma unroll
        for (int off = 16; off; off >>= 1) ss += __shfl_xor_sync(0xffffffffu, ss, off);
        float r = rsqrtf(ss);
        g_sn[(size_t)sidx * C_DIM + lane]      = __float2bfloat16(v0 * r);
        g_sn[(size_t)sidx * C_DIM + lane + 32] = __float2bfloat16(v1 * r);
    }
}

// ---------------------------------------------------------------------------
// mma.sync m16n8k16 bf16, fp32 accum
// ---------------------------------------------------------------------------
__device__ __forceinline__ void mma16816(float& d0, float& d1, float& d2, float& d3,
                                         uint32_t a0, uint32_t a1, uint32_t a2, uint32_t a3,
                                         uint32_t b0, uint32_t b1) {
    asm volatile(
        "mma.sync.aligned.m16n8k16.row.col.f32.bf16.bf16.f32 "
        "{%0,%1,%2,%3}, {%4,%5,%6,%7}, {%8,%9}, {%0,%1,%2,%3};"
        : "+f"(d0), "+f"(d1), "+f"(d2), "+f"(d3)
        : "r"(a0), "r"(a1), "r"(a2), "r"(a3), "r"(b0), "r"(b1));
}

// Branchless sorted insert of single value (5 FMNMX)
__device__ __forceinline__ void ins3(float v, float& t0, float& t1, float& t2) {
    float m0 = fminf(t0, v);
    t0 = fmaxf(t0, v);
    float m1 = fminf(t1, m0);
    t1 = fmaxf(t1, m0);
    t2 = fmaxf(t2, m1);
}

// Branchless insert of a PAIR (a,b): insert mx fully; mn <= mx <= new t0, so
// mn only needs the t1/t2 levels. 10 FMNMX per 2 values, zero divergence.
__device__ __forceinline__ void ins3_pair(float a, float b,
                                          float& t0, float& t1, float& t2) {
    float mx = fmaxf(a, b);
    float mn = fminf(a, b);
    float m0 = fminf(t0, mx);
    t0 = fmaxf(t0, mx);
    float m1 = fminf(t1, m0);
    t1 = fmaxf(t1, m0);
    t2 = fmaxf(t2, m1);
    float m2 = fminf(t1, mn);
    t1 = fmaxf(t1, mn);
    t2 = fmaxf(t2, m2);
}

// cp.async one 64-column support chunk into smem, zero-fill past M
__device__ __forceinline__ void load_chunk(int chunk, __nv_bfloat16* buf,
                                           const __nv_bfloat16* snj, int tid) {
    int m0 = chunk * 64;
#pragma unroll 1
    for (int i = tid; i < 512; i += 224) {
        int col = i >> 3, seg = i & 7;
        int m = m0 + col;
        int valid = (m < M_DIM);
        const __nv_bfloat16* src = snj + (size_t)(valid ? m : 0) * C_DIM + seg * 8;
        uint32_t daddr = (uint32_t)__cvta_generic_to_shared(buf + col * SM_STRIDE + seg * 8);
        int sz = valid ? 16 : 0;
        asm volatile("cp.async.cg.shared.global [%0], [%1], 16, %2;"
                     :: "r"(daddr), "l"(src), "r"(sz));
    }
}

template <bool GUARD>
__device__ __forceinline__ void process_chunk(const __nv_bfloat16* sm,
                                              const uint32_t (&afr)[4][4][4],
                                              float (&t0)[4][2], float (&t1)[4][2], float (&t2)[4][2],
                                              int lane, int m0) {
    int colq = lane >> 2;
    int kq = (lane & 3) * 2;
#pragma unroll
    for (int st = 0; st < 8; st++) {
        uint32_t bf[4][2];
        const __nv_bfloat16* base = sm + (st * 8 + colq) * SM_STRIDE + kq;
#pragma unroll
        for (int kk = 0; kk < 4; kk++) {
            bf[kk][0] = *(const uint32_t*)(base + kk * 16);
            bf[kk][1] = *(const uint32_t*)(base + kk * 16 + 8);
        }
        int mcol = m0 + st * 8 + (lane & 3) * 2;  // column of d0/d2; d1/d3 at mcol+1
#pragma unroll
        for (int g = 0; g < 4; g++) {
            float d0 = 0.f, d1 = 0.f, d2 = 0.f, d3 = 0.f;
#pragma unroll
            for (int kk = 0; kk < 4; kk++)
                mma16816(d0, d1, d2, d3,
                         afr[g][kk][0], afr[g][kk][1], afr[g][kk][2], afr[g][kk][3],
                         bf[kk][0], bf[kk][1]);
            if (GUARD) {
                // Tail chunk: mask out-of-range columns (cols are zero-filled,
                // which could still beat real negatives) with -inf sentinels.
                bool v0 = mcol < M_DIM, v1 = mcol + 1 < M_DIM;
                d0 = v0 ? d0 : -1e30f;
                d2 = v0 ? d2 : -1e30f;
                d1 = v1 ? d1 : -1e30f;
                d3 = v1 ? d3 : -1e30f;
            }
            ins3_pair(d0, d1, t0[g][0], t1[g][0], t2[g][0]);
            ins3_pair(d2, d3, t0[g][1], t1[g][1], t2[g][1]);
        }
    }
}

// ---------------------------------------------------------------------------
// Main fused kernel: CTA = (class j, image b). 7 warps * 4 groups * 16 rows
// = 448 rows (441 valid). A fragments register-resident for the whole M sweep.
// ---------------------------------------------------------------------------
__global__ __launch_bounds__(224, 2)
void knn_main(float* __restrict__ out) {
    __shared__ __nv_bfloat16 sbuf[2][64 * SM_STRIDE];
    __shared__ float wsum[7];

    int j = blockIdx.x;
    int b = blockIdx.y;
    int tid = threadIdx.x;
    int warp = tid >> 5;
    int lane = tid & 31;

    const __nv_bfloat16* snj = g_sn + (size_t)j * M_DIM * C_DIM;

    // Load A fragments (held in registers the whole kernel). Rows >= 441 -> zeros.
    uint32_t afr[4][4][4];
    int c0 = (lane & 3) * 2;
#pragma unroll
    for (int g = 0; g < 4; g++) {
        int r0 = (warp * 4 + g) * 16 + (lane >> 2);
        int r1 = r0 + 8;
        bool v0 = r0 < P_DIM, v1 = r1 < P_DIM;
        const uint32_t* row0 = (const uint32_t*)(g_qn + ((size_t)b * P_DIM + (v0 ? r0 : 0)) * C_DIM);
        const uint32_t* row1 = (const uint32_t*)(g_qn + ((size_t)b * P_DIM + (v1 ? r1 : 0)) * C_DIM);
#pragma unroll
        for (int kk = 0; kk < 4; kk++) {
            int cw = (c0 + kk * 16) >> 1;  // u32 index into the 64-ch row
            afr[g][kk][0] = v0 ? row0[cw]     : 0u;
            afr[g][kk][1] = v1 ? row1[cw]     : 0u;
            afr[g][kk][2] = v0 ? row0[cw + 4] : 0u;
            afr[g][kk][3] = v1 ? row1[cw + 4] : 0u;
        }
    }

    float t0[4][2], t1[4][2], t2[4][2];
#pragma unroll
    for (int g = 0; g < 4; g++)
#pragma unroll
        for (int h = 0; h < 2; h++) { t0[g][h] = -1e30f; t1[g][h] = -1e30f; t2[g][h] = -1e30f; }

    load_chunk(0, sbuf[0], snj, tid);
    asm volatile("cp.async.commit_group;");

#pragma unroll 1
    for (int chunk = 0; chunk < NCHUNK; chunk++) {
        if (chunk + 1 < NCHUNK) load_chunk(chunk + 1, sbuf[(chunk + 1) & 1], snj, tid);
        asm volatile("cp.async.commit_group;");
        asm volatile("cp.async.wait_group 1;");
        __syncthreads();
        const __nv_bfloat16* sm = sbuf[chunk & 1];
        if (chunk == NCHUNK - 1)
            process_chunk<true>(sm, afr, t0, t1, t2, lane, chunk * 64);
        else
            process_chunk<false>(sm, afr, t0, t1, t2, lane, chunk * 64);
        __syncthreads();
    }

    // Merge top-3 across the 4 lanes of each quad (they saw disjoint columns)
    float acc = 0.f;
#pragma unroll
    for (int g = 0; g < 4; g++) {
#pragma unroll
        for (int h = 0; h < 2; h++) {
            float x0 = t0[g][h], x1 = t1[g][h], x2 = t2[g][h];
#pragma unroll
            for (int off = 1; off <= 2; off <<= 1) {
                float y0 = __shfl_xor_sync(0xffffffffu, x0, off);
                float y1 = __shfl_xor_sync(0xffffffffu, x1, off);
                float y2 = __shfl_xor_sync(0xffffffffu, x2, off);
                ins3(y0, x0, x1, x2);
                ins3(y1, x0, x1, x2);
                ins3(y2, x0, x1, x2);
            }
            acc += x0 + x1 + x2;
        }
    }
    if (lane & 3) acc = 0.f;  // each quad's 4 lanes now hold identical triples
#pragma unroll
    for (int off = 16; off; off >>= 1) acc += __shfl_xor_sync(0xffffffffu, acc, off);
    if (lane == 0) wsum[warp] = acc;
    __syncthreads();
    if (tid == 0) {
        float s = 0.f;
#pragma unroll
        for (int w = 0; w < 7; w++) s += wsum[w];
        out[b * NWAY + j] = s;  // inner[b][j]
    }
}

// ---------------------------------------------------------------------------
extern "C" void kernel_launch(void* const* d_in, const int* in_sizes, int n_in,
                              void* d_out, int out_size) {
    const float* q = (const float*)d_in[0];
    const float* S = (const float*)d_in[1];
    float* out = (float*)d_out;

    int ndesc = NROWS + NDESC_S;
    prep_all<<<(ndesc + 7) / 8, 256>>>(q, S);
    knn_main<<<dim3(NWAY, B_IMG), 224>>>(out);
}

// round 10
// speedup vs baseline: 1.8343x; 1.1962x over previous
#include <cuda_runtime.h>
#include <cuda_bf16.h>
#include <cuda_fp16.h>
#include <cstdint>
#include <cstddef>

// Problem dims (fixed by dataset)
#define B_IMG   128
#define C_DIM   64
#define P_DIM   441           // 21*21
#define NWAY    50
#define M_DIM   2205
#define NROWS   (B_IMG * P_DIM)     // 56448
#define NDESC_S (NWAY * M_DIM)      // 110250
#define NCHUNK  35                  // ceil(2205/64)
#define SM_STRIDE 72                // bf16 elems per support-descriptor row in smem (144B, conflict-free)

// Scratch: normalized bf16 descriptors (static device globals — no allocation)
__device__ __nv_bfloat16 g_qn[(size_t)NROWS * C_DIM];            // [row][c], row = b*441+p
__device__ __nv_bfloat16 g_sn[(size_t)NDESC_S * C_DIM];          // [j][m][c]

// ---------------------------------------------------------------------------
// Precompute: L2-normalize descriptors over C=64, convert to bf16.
// ---------------------------------------------------------------------------
__global__ void prep_all(const float* __restrict__ q, const float* __restrict__ S) {
    int idx = blockIdx.x * 8 + (threadIdx.x >> 5);
    int lane = threadIdx.x & 31;
    if (idx < NROWS) {
        int b = idx / P_DIM, p = idx % P_DIM;
        const float* base = q + (size_t)b * C_DIM * P_DIM + p;
        float v0 = base[(size_t)lane * P_DIM];
        float v1 = base[(size_t)(lane + 32) * P_DIM];
        float ss = v0 * v0 + v1 * v1;
#pragma unroll
        for (int off = 16; off; off >>= 1) ss += __shfl_xor_sync(0xffffffffu, ss, off);
        float r = rsqrtf(ss);
        g_qn[(size_t)idx * C_DIM + lane]      = __float2bfloat16(v0 * r);
        g_qn[(size_t)idx * C_DIM + lane + 32] = __float2bfloat16(v1 * r);
    } else if (idx < NROWS + NDESC_S) {
        int sidx = idx - NROWS;
        int j = sidx / M_DIM, m = sidx % M_DIM;
        const float* base = S + (size_t)j * C_DIM * M_DIM + m;
        float v0 = base[(size_t)lane * M_DIM];
        float v1 = base[(size_t)(lane + 32) * M_DIM];
        float ss = v0 * v0 + v1 * v1;
#pragma unroll
        for (int off = 16; off; off >>= 1) ss += __shfl_xor_sync(0xffffffffu, ss, off);
        float r = rsqrtf(ss);
        g_sn[(size_t)sidx * C_DIM + lane]      = __float2bfloat16(v0 * r);
        g_sn[(size_t)sidx * C_DIM + lane + 32] = __float2bfloat16(v1 * r);
    }
}

// ---------------------------------------------------------------------------
// mma.sync m16n8k16 bf16, fp32 accum
// ---------------------------------------------------------------------------
__device__ __forceinline__ void mma16816(float& d0, float& d1, float& d2, float& d3,
                                         uint32_t a0, uint32_t a1, uint32_t a2, uint32_t a3,
                                         uint32_t b0, uint32_t b1) {
    asm volatile(
        "mma.sync.aligned.m16n8k16.row.col.f32.bf16.bf16.f32 "
        "{%0,%1,%2,%3}, {%4,%5,%6,%7}, {%8,%9}, {%0,%1,%2,%3};"
        : "+f"(d0), "+f"(d1), "+f"(d2), "+f"(d3)
        : "r"(a0), "r"(a1), "r"(a2), "r"(a3), "r"(b0), "r"(b1));
}

// Branchless sorted insert of single fp32 value (5 FMNMX) — final merges only
__device__ __forceinline__ void ins3(float v, float& t0, float& t1, float& t2) {
    float m0 = fminf(t0, v);
    t0 = fmaxf(t0, v);
    float m1 = fminf(t1, m0);
    t1 = fmaxf(t1, m0);
    t2 = fmaxf(t2, m1);
}

// Packed half2 sorted insert: one instruction per op covers BOTH sub-trackers
// (lane0 tracks even columns, lane1 odd columns). 5 HMNMX2 per 2 values.
__device__ __forceinline__ void hins3(__half2 v, __half2& t0, __half2& t1, __half2& t2) {
    __half2 m0 = __hmin2(t0, v);
    t0 = __hmax2(t0, v);
    __half2 m1 = __hmin2(t1, m0);
    t1 = __hmax2(t1, m0);
    t2 = __hmax2(t2, m1);
}

// cp.async one 64-column support chunk into smem, zero-fill past M
__device__ __forceinline__ void load_chunk(int chunk, __nv_bfloat16* buf,
                                           const __nv_bfloat16* snj, int tid) {
    int m0 = chunk * 64;
#pragma unroll 1
    for (int i = tid; i < 512; i += 224) {
        int col = i >> 3, seg = i & 7;
        int m = m0 + col;
        int valid = (m < M_DIM);
        const __nv_bfloat16* src = snj + (size_t)(valid ? m : 0) * C_DIM + seg * 8;
        uint32_t daddr = (uint32_t)__cvta_generic_to_shared(buf + col * SM_STRIDE + seg * 8);
        int sz = valid ? 16 : 0;
        asm volatile("cp.async.cg.shared.global [%0], [%1], 16, %2;"
                     :: "r"(daddr), "l"(src), "r"(sz));
    }
}

template <bool GUARD>
__device__ __forceinline__ void process_chunk(const __nv_bfloat16* sm,
                                              const uint32_t (&afr)[4][4][4],
                                              __half2 (&T0)[4][2], __half2 (&T1)[4][2], __half2 (&T2)[4][2],
                                              int lane, int m0) {
    int colq = lane >> 2;
    int kq = (lane & 3) * 2;
#pragma unroll
    for (int st = 0; st < 8; st++) {
        uint32_t bf[4][2];
        const __nv_bfloat16* base = sm + (st * 8 + colq) * SM_STRIDE + kq;
#pragma unroll
        for (int kk = 0; kk < 4; kk++) {
            bf[kk][0] = *(const uint32_t*)(base + kk * 16);
            bf[kk][1] = *(const uint32_t*)(base + kk * 16 + 8);
        }
        int mcol = m0 + st * 8 + (lane & 3) * 2;  // column of d0/d2; d1/d3 at mcol+1
#pragma unroll
        for (int g = 0; g < 4; g++) {
            float d0 = 0.f, d1 = 0.f, d2 = 0.f, d3 = 0.f;
#pragma unroll
            for (int kk = 0; kk < 4; kk++)
                mma16816(d0, d1, d2, d3,
                         afr[g][kk][0], afr[g][kk][1], afr[g][kk][2], afr[g][kk][3],
                         bf[kk][0], bf[kk][1]);
            if (GUARD) {
                // Tail chunk: mask out-of-range columns with large-negative
                // sentinels (→ -inf in half, max-only propagation, safe).
                bool v0 = mcol < M_DIM, v1 = mcol + 1 < M_DIM;
                d0 = v0 ? d0 : -1e30f;
                d2 = v0 ? d2 : -1e30f;
                d1 = v1 ? d1 : -1e30f;
                d3 = v1 ? d3 : -1e30f;
            }
            __half2 v01 = __float22half2_rn(make_float2(d0, d1));
            __half2 v23 = __float22half2_rn(make_float2(d2, d3));
            hins3(v01, T0[g][0], T1[g][0], T2[g][0]);
            hins3(v23, T0[g][1], T1[g][1], T2[g][1]);
        }
    }
}

// ---------------------------------------------------------------------------
// Main fused kernel: CTA = (class j, image b). 7 warps * 4 groups * 16 rows
// = 448 rows (441 valid). A fragments register-resident for the whole M sweep.
// ---------------------------------------------------------------------------
__global__ __launch_bounds__(224, 2)
void knn_main(float* __restrict__ out) {
    __shared__ __nv_bfloat16 sbuf[2][64 * SM_STRIDE];
    __shared__ float wsum[7];

    int j = blockIdx.x;
    int b = blockIdx.y;
    int tid = threadIdx.x;
    int warp = tid >> 5;
    int lane = tid & 31;

    const __nv_bfloat16* snj = g_sn + (size_t)j * M_DIM * C_DIM;

    // Load A fragments (held in registers the whole kernel). Rows >= 441 -> zeros.
    uint32_t afr[4][4][4];
    int c0 = (lane & 3) * 2;
#pragma unroll
    for (int g = 0; g < 4; g++) {
        int r0 = (warp * 4 + g) * 16 + (lane >> 2);
        int r1 = r0 + 8;
        bool v0 = r0 < P_DIM, v1 = r1 < P_DIM;
        const uint32_t* row0 = (const uint32_t*)(g_qn + ((size_t)b * P_DIM + (v0 ? r0 : 0)) * C_DIM);
        const uint32_t* row1 = (const uint32_t*)(g_qn + ((size_t)b * P_DIM + (v1 ? r1 : 0)) * C_DIM);
#pragma unroll
        for (int kk = 0; kk < 4; kk++) {
            int cw = (c0 + kk * 16) >> 1;  // u32 index into the 64-ch row
            afr[g][kk][0] = v0 ? row0[cw]     : 0u;
            afr[g][kk][1] = v1 ? row1[cw]     : 0u;
            afr[g][kk][2] = v0 ? row0[cw + 4] : 0u;
            afr[g][kk][3] = v1 ? row1[cw + 4] : 0u;
        }
    }

    // Packed trackers: lane0 = even columns, lane1 = odd columns
    __half2 T0[4][2], T1[4][2], T2[4][2];
    __half2 ninf = __float2half2_rn(-1e4f);
#pragma unroll
    for (int g = 0; g < 4; g++)
#pragma unroll
        for (int h = 0; h < 2; h++) { T0[g][h] = ninf; T1[g][h] = ninf; T2[g][h] = ninf; }

    load_chunk(0, sbuf[0], snj, tid);
    asm volatile("cp.async.commit_group;");

#pragma unroll 1
    for (int chunk = 0; chunk < NCHUNK; chunk++) {
        if (chunk + 1 < NCHUNK) load_chunk(chunk + 1, sbuf[(chunk + 1) & 1], snj, tid);
        asm volatile("cp.async.commit_group;");
        asm volatile("cp.async.wait_group 1;");
        __syncthreads();
        const __nv_bfloat16* sm = sbuf[chunk & 1];
        if (chunk == NCHUNK - 1)
            process_chunk<true>(sm, afr, T0, T1, T2, lane, chunk * 64);
        else
            process_chunk<false>(sm, afr, T0, T1, T2, lane, chunk * 64);
        __syncthreads();
    }

    // Merge the two packed sub-trackers into an fp32 triple, then across the
    // 4 lanes of each quad (they saw disjoint columns).
    float acc = 0.f;
#pragma unroll
    for (int g = 0; g < 4; g++) {
#pragma unroll
        for (int h = 0; h < 2; h++) {
            float2 a0 = __half22float2(T0[g][h]);
            float2 a1 = __half22float2(T1[g][h]);
            float2 a2 = __half22float2(T2[g][h]);
            float x0 = fmaxf(a0.x, a0.y);
            float x1 = fminf(a0.x, a0.y);
            float x2 = -1e30f;
            ins3(a1.x, x0, x1, x2);
            ins3(a1.y, x0, x1, x2);
            ins3(a2.x, x0, x1, x2);
            ins3(a2.y, x0, x1, x2);
#pragma unroll
            for (int off = 1; off <= 2; off <<= 1) {
                float y0 = __shfl_xor_sync(0xffffffffu, x0, off);
                float y1 = __shfl_xor_sync(0xffffffffu, x1, off);
                float y2 = __shfl_xor_sync(0xffffffffu, x2, off);
                ins3(y0, x0, x1, x2);
                ins3(y1, x0, x1, x2);
                ins3(y2, x0, x1, x2);
            }
            acc += x0 + x1 + x2;
        }
    }
    if (lane & 3) acc = 0.f;  // each quad's 4 lanes now hold identical triples
#pragma unroll
    for (int off = 16; off; off >>= 1) acc += __shfl_xor_sync(0xffffffffu, acc, off);
    if (lane == 0) wsum[warp] = acc;
    __syncthreads();
    if (tid == 0) {
        float s = 0.f;
#pragma unroll
        for (int w = 0; w < 7; w++) s += wsum[w];
        out[b * NWAY + j] = s;  // inner[b][j]
    }
}

// ---------------------------------------------------------------------------
extern "C" void kernel_launch(void* const* d_in, const int* in_sizes, int n_in,
                              void* d_out, int out_size) {
    const float* q = (const float*)d_in[0];
    const float* S = (const float*)d_in[1];
    float* out = (float*)d_out;

    int ndesc = NROWS + NDESC_S;
    prep_all<<<(ndesc + 7) / 8, 256>>>(q, S);
    knn_main<<<dim3(NWAY, B_IMG), 224>>>(out);
}

// round 12
// speedup vs baseline: 1.9626x; 1.0699x over previous
#include <cuda_runtime.h>
#include <cuda_fp16.h>
#include <cstdint>
#include <cstddef>

// Problem dims (fixed by dataset)
#define B_IMG   128
#define C_DIM   64
#define P_DIM   441           // 21*21
#define NWAY    50
#define M_DIM   2205
#define NROWS   (B_IMG * P_DIM)     // 56448
#define NDESC_S (NWAY * M_DIM)      // 110250
#define NCHUNK  35                  // ceil(2205/64)
#define SM_STRIDE 72                // fp16 elems per support-descriptor row in smem (144B, conflict-free)

// Scratch: normalized fp16 descriptors (static device globals — no allocation)
__device__ __half g_qn[(size_t)NROWS * C_DIM];            // [row][c], row = b*441+p
__device__ __half g_sn[(size_t)NDESC_S * C_DIM];          // [j][m][c]

// ---------------------------------------------------------------------------
// Precompute: L2-normalize descriptors over C=64, convert to fp16.
// (|v| <= 1 after normalization: fp16 gives 11-bit mantissa here, beats bf16.)
// ---------------------------------------------------------------------------
__global__ void prep_all(const float* __restrict__ q, const float* __restrict__ S) {
    int idx = blockIdx.x * 8 + (threadIdx.x >> 5);
    int lane = threadIdx.x & 31;
    if (idx < NROWS) {
        int b = idx / P_DIM, p = idx % P_DIM;
        const float* base = q + (size_t)b * C_DIM * P_DIM + p;
        float v0 = base[(size_t)lane * P_DIM];
        float v1 = base[(size_t)(lane + 32) * P_DIM];
        float ss = v0 * v0 + v1 * v1;
#pragma unroll
        for (int off = 16; off; off >>= 1) ss += __shfl_xor_sync(0xffffffffu, ss, off);
        float r = rsqrtf(ss);
        g_qn[(size_t)idx * C_DIM + lane]      = __float2half_rn(v0 * r);
        g_qn[(size_t)idx * C_DIM + lane + 32] = __float2half_rn(v1 * r);
    } else if (idx < NROWS + NDESC_S) {
        int sidx = idx - NROWS;
        int j = sidx / M_DIM, m = sidx % M_DIM;
        const float* base = S + (size_t)j * C_DIM * M_DIM + m;
        float v0 = base[(size_t)lane * M_DIM];
        float v1 = base[(size_t)(lane + 32) * M_DIM];
        float ss = v0 * v0 + v1 * v1;
#pragma unroll
        for (int off = 16; off; off >>= 1) ss += __shfl_xor_sync(0xffffffffu, ss, off);
        float r = rsqrtf(ss);
        g_sn[(size_t)sidx * C_DIM + lane]      = __float2half_rn(v0 * r);
        g_sn[(size_t)sidx * C_DIM + lane + 32] = __float2half_rn(v1 * r);
    }
}

// ---------------------------------------------------------------------------
// mma.sync m16n8k16 f16 x f16 -> f16 accum. D/C = {c0,c1} packed half2:
// c0 = (col n, col n+1) of row (lane>>2); c1 = same cols of row+8.
// ---------------------------------------------------------------------------
__device__ __forceinline__ void mma16816_f16(uint32_t& c0, uint32_t& c1,
                                             uint32_t a0, uint32_t a1, uint32_t a2, uint32_t a3,
                                             uint32_t b0, uint32_t b1) {
    asm volatile(
        "mma.sync.aligned.m16n8k16.row.col.f16.f16.f16.f16 "
        "{%0,%1}, {%2,%3,%4,%5}, {%6,%7}, {%0,%1};"
        : "+r"(c0), "+r"(c1)
        : "r"(a0), "r"(a1), "r"(a2), "r"(a3), "r"(b0), "r"(b1));
}

// Branchless sorted insert of single fp32 value (5 FMNMX) — final merges only
__device__ __forceinline__ void ins3(float v, float& t0, float& t1, float& t2) {
    float m0 = fminf(t0, v);
    t0 = fmaxf(t0, v);
    float m1 = fminf(t1, m0);
    t1 = fmaxf(t1, m0);
    t2 = fmaxf(t2, m1);
}

// Packed half2 sorted insert: .x/.y are independent sub-trackers (even/odd col).
// 5 HMNMX2 per 2 values, fed DIRECTLY by the f16 MMA output (no conversion).
__device__ __forceinline__ void hins3(__half2 v, __half2& t0, __half2& t1, __half2& t2) {
    __half2 m0 = __hmin2(t0, v);
    t0 = __hmax2(t0, v);
    __half2 m1 = __hmin2(t1, m0);
    t1 = __hmax2(t1, m0);
    t2 = __hmax2(t2, m1);
}

// cp.async one 64-column support chunk into smem, zero-fill past M
__device__ __forceinline__ void load_chunk(int chunk, __half* buf,
                                           const __half* snj, int tid) {
    int m0 = chunk * 64;
#pragma unroll 1
    for (int i = tid; i < 512; i += 224) {
        int col = i >> 3, seg = i & 7;
        int m = m0 + col;
        int valid = (m < M_DIM);
        const __half* src = snj + (size_t)(valid ? m : 0) * C_DIM + seg * 8;
        uint32_t daddr = (uint32_t)__cvta_generic_to_shared(buf + col * SM_STRIDE + seg * 8);
        int sz = valid ? 16 : 0;
        asm volatile("cp.async.cg.shared.global [%0], [%1], 16, %2;"
                     :: "r"(daddr), "l"(src), "r"(sz));
    }
}

template <bool GUARD>
__device__ __forceinline__ void process_chunk(const __half* sm,
                                              const uint32_t (&afr)[4][4][4],
                                              __half2 (&T0)[4][2], __half2 (&T1)[4][2], __half2 (&T2)[4][2],
                                              int lane, int m0) {
    int colq = lane >> 2;
    int kq = (lane & 3) * 2;
    const __half NINF = __float2half(-60000.0f);
#pragma unroll
    for (int st = 0; st < 8; st++) {
        uint32_t bf[4][2];
        const __half* base = sm + (st * 8 + colq) * SM_STRIDE + kq;
#pragma unroll
        for (int kk = 0; kk < 4; kk++) {
            bf[kk][0] = *(const uint32_t*)(base + kk * 16);
            bf[kk][1] = *(const uint32_t*)(base + kk * 16 + 8);
        }
        int mcol = m0 + st * 8 + (lane & 3) * 2;  // even col of this thread's pair
#pragma unroll
        for (int g = 0; g < 4; g++) {
            uint32_t c0 = 0u, c1 = 0u;  // half2 zeros
#pragma unroll
            for (int kk = 0; kk < 4; kk++)
                mma16816_f16(c0, c1,
                             afr[g][kk][0], afr[g][kk][1], afr[g][kk][2], afr[g][kk][3],
                             bf[kk][0], bf[kk][1]);
            __half2 v0 = *reinterpret_cast<__half2*>(&c0);  // row r:   (even, odd)
            __half2 v1 = *reinterpret_cast<__half2*>(&c1);  // row r+8: (even, odd)
            if (GUARD) {
                // Tail chunk: mask out-of-range columns with -inf sentinels.
                bool ve = mcol < M_DIM, vo = mcol + 1 < M_DIM;
                v0.x = ve ? v0.x : NINF;  v0.y = vo ? v0.y : NINF;
                v1.x = ve ? v1.x : NINF;  v1.y = vo ? v1.y : NINF;
            }
            hins3(v0, T0[g][0], T1[g][0], T2[g][0]);
            hins3(v1, T0[g][1], T1[g][1], T2[g][1]);
        }
    }
}

// ---------------------------------------------------------------------------
// Main fused kernel: CTA = (class j, image b). 7 warps * 4 groups * 16 rows
// = 448 rows (441 valid). A fragments register-resident for the whole M sweep.
// ---------------------------------------------------------------------------
__global__ __launch_bounds__(224, 2)
void knn_main(float* __restrict__ out) {
    __shared__ __half sbuf[2][64 * SM_STRIDE];
    __shared__ float wsum[7];

    int j = blockIdx.x;
    int b = blockIdx.y;
    int tid = threadIdx.x;
    int warp = tid >> 5;
    int lane = tid & 31;

    const __half* snj = g_sn + (size_t)j * M_DIM * C_DIM;

    // Load A fragments (held in registers the whole kernel). Rows >= 441 -> zeros.
    uint32_t afr[4][4][4];
    int c0i = (lane & 3) * 2;
#pragma unroll
    for (int g = 0; g < 4; g++) {
        int r0 = (warp * 4 + g) * 16 + (lane >> 2);
        int r1 = r0 + 8;
        bool v0 = r0 < P_DIM, v1 = r1 < P_DIM;
        const uint32_t* row0 = (const uint32_t*)(g_qn + ((size_t)b * P_DIM + (v0 ? r0 : 0)) * C_DIM);
        const uint32_t* row1 = (const uint32_t*)(g_qn + ((size_t)b * P_DIM + (v1 ? r1 : 0)) * C_DIM);
#pragma unroll
        for (int kk = 0; kk < 4; kk++) {
            int cw = (c0i + kk * 16) >> 1;  // u32 index into the 64-ch row
            afr[g][kk][0] = v0 ? row0[cw]     : 0u;
            afr[g][kk][1] = v1 ? row1[cw]     : 0u;
            afr[g][kk][2] = v0 ? row0[cw + 4] : 0u;
            afr[g][kk][3] = v1 ? row1[cw + 4] : 0u;
        }
    }

    // Packed trackers: [g][row-half]; .x = even cols, .y = odd cols
    __half2 T0[4][2], T1[4][2], T2[4][2];
    __half2 ninf = __float2half2_rn(-60000.0f);
#pragma unroll
    for (int g = 0; g < 4; g++)
#pragma unroll
        for (int h = 0; h < 2; h++) { T0[g][h] = ninf; T1[g][h] = ninf; T2[g][h] = ninf; }

    load_chunk(0, sbuf[0], snj, tid);
    asm volatile("cp.async.commit_group;");

#pragma unroll 1
    for (int chunk = 0; chunk < NCHUNK; chunk++) {
        if (chunk + 1 < NCHUNK) load_chunk(chunk + 1, sbuf[(chunk + 1) & 1], snj, tid);
        asm volatile("cp.async.commit_group;");
        asm volatile("cp.async.wait_group 1;");
        __syncthreads();
        const __half* sm = sbuf[chunk & 1];
        if (chunk == NCHUNK - 1)
            process_chunk<true>(sm, afr, T0, T1, T2, lane, chunk * 64);
        else
            process_chunk<false>(sm, afr, T0, T1, T2, lane, chunk * 64);
        __syncthreads();
    }

    // Merge packed sub-trackers into fp32 triples, then across each quad's 4
    // lanes (disjoint columns).
    float acc = 0.f;
#pragma unroll
    for (int g = 0; g < 4; g++) {
#pragma unroll
        for (int h = 0; h < 2; h++) {
            float2 a0 = __half22float2(T0[g][h]);
            float2 a1 = __half22float2(T1[g][h]);
            float2 a2 = __half22float2(T2[g][h]);
            float x0 = fmaxf(a0.x, a0.y);
            float x1 = fminf(a0.x, a0.y);
            float x2 = -1e30f;
            ins3(a1.x, x0, x1, x2);
            ins3(a1.y, x0, x1, x2);
            ins3(a2.x, x0, x1, x2);
            ins3(a2.y, x0, x1, x2);
#pragma unroll
            for (int off = 1; off <= 2; off <<= 1) {
                float y0 = __shfl_xor_sync(0xffffffffu, x0, off);
                float y1 = __shfl_xor_sync(0xffffffffu, x1, off);
                float y2 = __shfl_xor_sync(0xffffffffu, x2, off);
                ins3(y0, x0, x1, x2);
                ins3(y1, x0, x1, x2);
                ins3(y2, x0, x1, x2);
            }
            acc += x0 + x1 + x2;
        }
    }
    if (lane & 3) acc = 0.f;  // each quad's 4 lanes now hold identical triples
#pragma unroll
    for (int off = 16; off; off >>= 1) acc += __shfl_xor_sync(0xffffffffu, acc, off);
    if (lane == 0) wsum[warp] = acc;
    __syncthreads();
    if (tid == 0) {
        float s = 0.f;
#pragma unroll
        for (int w = 0; w < 7; w++) s += wsum[w];
        out[b * NWAY + j] = s;  // inner[b][j]
    }
}

// ---------------------------------------------------------------------------
extern "C" void kernel_launch(void* const* d_in, const int* in_sizes, int n_in,
                              void* d_out, int out_size) {
    const float* q = (const float*)d_in[0];
    const float* S = (const float*)d_in[1];
    float* out = (float*)d_out;

    int ndesc = NROWS + NDESC_S;
    prep_all<<<(ndesc + 7) / 8, 256>>>(q, S);
    knn_main<<<dim3(NWAY, B_IMG), 224>>>(out);
}